// round 14
// baseline (speedup 1.0000x reference)
#include <cuda_runtime.h>
#include <cuda_bf16.h>
#include <cuda_pipeline.h>
#include <math.h>

#define KK   64
#define DD   320
#define NN   2048
#define MM   128
#define SS   (KK * MM)        // 8192
#define DB   4                // dims per chunk (contiguous in feat)
#define NB   (DD / DB)        // 80 chunks per cloud
#define GPC  4                // gather blocks per cloud
#define CPB  (NB / GPC)       // 20 chunks per block
#define EPSN 1e-12f
#define FBLK 256              // fused blocks, 2 per SM, all co-resident
#define FTPB 512              // 16 warps
#define RPW  2                // rows per warp: 256*16*2 = 8192

// ---------------- device scratch ----------------
__device__ int   g_perm[KK * NN];        // sorted point index per cloud
__device__ int   g_off[SS];              // per-cloud exclusive prefix of counts
__device__ float g_counts[SS];
__device__ int   g_cls[SS];
__device__ float g_blkmax[KK];
__device__ float g_vpart[FBLK * DD];
__device__ float g_v[DD];
__device__ float g_msum_p[FBLK];
__device__ float g_mcnt_p[FBLK];
// tree barrier state: monotonic round counters (graph-replay safe)
__device__ int   g_leaf[3][16];
__device__ int   g_root[3];
__device__ int   g_flag[3];

// two-level grid barrier: 256 blocks -> 16 leaves -> root -> flag
__device__ __forceinline__ void gridbar(int which) {
    __syncthreads();
    if (threadIdx.x == 0) {
        __threadfence();
        int arr = atomicAdd(&g_leaf[which][blockIdx.x & 15], 1);
        int round = arr >> 4;              // 16 arrivals per leaf per round
        if ((arr & 15) == 15) {            // last of this leaf's round
            int ra = atomicAdd(&g_root[which], 1);
            if ((ra & 15) == 15) {         // last leaf of the round
                __threadfence();
                g_flag[which] = (ra >> 4) + 1;
            }
        }
        while (*(volatile int*)&g_flag[which] < round + 1) __nanosleep(32);
        __threadfence();
    }
    __syncthreads();
}

// ---------------- A: counts / class mask / offsets / perm / blockmax ----
__global__ __launch_bounds__(512)
void k_counts(const float* __restrict__ label,
              const int*   __restrict__ clab) {
    __shared__ float s_cnt[MM];
    __shared__ float s_lbl[MM];
    __shared__ int   s_off[MM];
    __shared__ int   s_cur[MM];
    __shared__ float s_size[MM];
    int k = blockIdx.x;
    int tid = threadIdx.x;
    int lane = tid & 31;
    if (tid < MM) { s_cnt[tid] = 0.0f; s_lbl[tid] = 0.0f; }
    __syncthreads();
    const int base = k * NN;
    int4   c4 = ((const int4*)(clab + base))[tid];
    float4 l4 = ((const float4*)(label + base))[tid];
    atomicAdd(&s_cnt[c4.x], 1.0f); atomicAdd(&s_lbl[c4.x], l4.x);
    atomicAdd(&s_cnt[c4.y], 1.0f); atomicAdd(&s_lbl[c4.y], l4.y);
    atomicAdd(&s_cnt[c4.z], 1.0f); atomicAdd(&s_lbl[c4.z], l4.z);
    atomicAdd(&s_cnt[c4.w], 1.0f); atomicAdd(&s_lbl[c4.w], l4.w);
    __syncthreads();
    if (tid < 32) {   // warp exclusive scan of 128 counts
        int e0 = (int)s_cnt[lane * 4 + 0];
        int e1 = (int)s_cnt[lane * 4 + 1];
        int e2 = (int)s_cnt[lane * 4 + 2];
        int e3 = (int)s_cnt[lane * 4 + 3];
        int t  = e0 + e1 + e2 + e3;
        int pre = t;
        #pragma unroll
        for (int o = 1; o < 32; o <<= 1) {
            int nb = __shfl_up_sync(0xffffffffu, pre, o);
            if (lane >= o) pre += nb;
        }
        int ex = pre - t;
        s_off[lane * 4 + 0] = ex;
        s_off[lane * 4 + 1] = ex + e0;
        s_off[lane * 4 + 2] = ex + e0 + e1;
        s_off[lane * 4 + 3] = ex + e0 + e1 + e2;
    }
    __syncthreads();
    if (tid < MM) {
        int s = k * MM + tid;
        float c  = s_cnt[tid];
        float dn = fmaxf(c, 1.0f);
        float lm = s_lbl[tid] / dn;
        int cls  = (lm > 0.5f) && (c > 0.0f);
        g_counts[s] = c;
        g_cls[s]    = cls;
        g_off[s]    = s_off[tid];
        s_cur[tid]  = s_off[tid];
        s_size[tid] = cls ? c : 0.0f;
    }
    __syncthreads();
    if (tid < 32) {   // per-cloud max size (plain store)
        float m = fmaxf(fmaxf(s_size[lane], s_size[lane + 32]),
                        fmaxf(s_size[lane + 64], s_size[lane + 96]));
        #pragma unroll
        for (int o = 16; o > 0; o >>= 1)
            m = fmaxf(m, __shfl_xor_sync(0xffffffffu, m, o));
        if (lane == 0) g_blkmax[k] = m;
    }
    {
        int n0 = tid * 4;
        int p;
        p = atomicAdd(&s_cur[c4.x], 1); g_perm[base + p] = n0 + 0;
        p = atomicAdd(&s_cur[c4.y], 1); g_perm[base + p] = n0 + 1;
        p = atomicAdd(&s_cur[c4.z], 1); g_perm[base + p] = n0 + 2;
        p = atomicAdd(&s_cur[c4.w], 1); g_perm[base + p] = n0 + 3;
    }
}

// ---------------- B: persistent double-buffered gather ----------------
// 256 blocks (2/SM, one wave). Block (k, part) owns 20 consecutive 4-dim
// chunks. cp.async prefetches chunk ch+1 while chunk ch is reduced, keeping
// the DRAM stream saturated. Perm staged once per block.
__global__ __launch_bounds__(512)
void k_gather(const float* __restrict__ feat,
              float*       __restrict__ out_cm) {
    __shared__ __align__(16) float s_buf[2][DB * NN];     // 64 KB
    __shared__ __align__(16) int   s_perm[NN];            // 8 KB
    __shared__ int   s_off[MM + 1];
    __shared__ float s_red[3][MM][DB];                    // 6 KB
    int k    = blockIdx.x / GPC;
    int part = blockIdx.x % GPC;
    int tid  = threadIdx.x;

    ((int4*)s_perm)[tid] = ((const int4*)(g_perm + k * NN))[tid];
    if (tid < MM) s_off[tid] = g_off[k * MM + tid];
    if (tid == 0) s_off[MM] = NN;

    const float* fcloud = feat + (size_t)k * DD * NN + (size_t)(part * CPB) * DB * NN;

    // prologue: prefetch chunk 0
    #pragma unroll
    for (int i = 0; i < 4; ++i) {
        int idx = (tid + i * 512) * 4;
        __pipeline_memcpy_async(&s_buf[0][idx], fcloud + idx, 16);
    }
    __pipeline_commit();

    __syncthreads();                  // staging (s_perm/s_off) visible to all

    int c = tid & (MM - 1);
    int q = tid >> 7;                 // 0..3
    int st = s_off[c];
    int en = s_off[c + 1];

    for (int cc = 0; cc < CPB; ++cc) {
        int cur = cc & 1;
        if (cc + 1 < CPB) {           // prefetch next chunk into other buffer
            const float* src = fcloud + (size_t)(cc + 1) * DB * NN;
            #pragma unroll
            for (int i = 0; i < 4; ++i) {
                int idx = (tid + i * 512) * 4;
                __pipeline_memcpy_async(&s_buf[1 - cur][idx], src + idx, 16);
            }
            __pipeline_commit();
            __pipeline_wait_prior(1); // current chunk's group complete
        } else {
            __pipeline_wait_prior(0);
        }
        __syncthreads();              // full buffer visible to all

        const float* bufp = s_buf[cur];
        float a0 = 0.f, a1 = 0.f, a2 = 0.f, a3 = 0.f;
        for (int p = st + q; p < en; p += 4) {
            int pt = s_perm[p];
            a0 += bufp[0 * NN + pt];
            a1 += bufp[1 * NN + pt];
            a2 += bufp[2 * NN + pt];
            a3 += bufp[3 * NN + pt];
        }
        if (q) {
            s_red[q - 1][c][0] = a0; s_red[q - 1][c][1] = a1;
            s_red[q - 1][c][2] = a2; s_red[q - 1][c][3] = a3;
        }
        __syncthreads();
        if (q == 0) {
            #pragma unroll
            for (int r = 0; r < 3; ++r) {
                a0 += s_red[r][c][0]; a1 += s_red[r][c][1];
                a2 += s_red[r][c][2]; a3 += s_red[r][c][3];
            }
            int s = k * MM + c;
            float dn = fmaxf(g_counts[s], 1.0f);
            int dbase = (part * CPB + cc) * DB;
            float4 o = make_float4(a0 / dn, a1 / dn, a2 / dn, a3 / dn);
            *(float4*)(out_cm + (size_t)s * DD + dbase) = o;
        }
        // next iteration's prefetch targets the buffer compute(cc-1) used;
        // the s_red __syncthreads above already ordered those reads.
    }
}

// ---------------- F: fused norms + v + sim + mean + clean (R11/R12) ---------
__global__ void __launch_bounds__(FTPB, 2)
k_fused(const float* __restrict__ cm,
        float* __restrict__ out_sim,
        float* __restrict__ out_clean) {
    __shared__ __align__(16) float s_v[DD];
    __shared__ float s_ms[16];
    __shared__ float s_mc[16];
    __shared__ float s_md;
    __shared__ float s_mean;
    __shared__ float s_red[32];
    int tid  = threadIdx.x;
    int warp = tid >> 5;
    int lane = tid & 31;
    const float4 z4 = make_float4(0.f, 0.f, 0.f, 0.f);

    if (tid < DD) s_v[tid] = 0.0f;
    if (warp == 0) {   // maxden from per-cloud maxes
        float m = fmaxf(g_blkmax[lane], g_blkmax[lane + 32]);
        #pragma unroll
        for (int o = 16; o > 0; o >>= 1)
            m = fmaxf(m, __shfl_xor_sync(0xffffffffu, m, o));
        if (lane == 0) s_md = fmaxf(m, 1.0f);
    }

    const int base = blockIdx.x * (16 * RPW) + warp * RPW;

    float4 x0[RPW], x1[RPW], x2[RPW];
    #pragma unroll
    for (int i = 0; i < RPW; ++i) {
        const float4* rp = (const float4*)(cm + (size_t)(base + i) * DD);
        x0[i] = rp[lane];
        x1[i] = rp[32 + lane];
        x2[i] = (lane < 16) ? rp[64 + lane] : z4;
    }
    __syncthreads();
    float maxden = s_md;

    float bfac[RPW];
    int   cls[RPW];
    float4 a0 = z4, a1 = z4, a2 = z4;
    #pragma unroll
    for (int i = 0; i < RPW; ++i) {
        int s = base + i;
        float ss = x0[i].x * x0[i].x + x0[i].y * x0[i].y + x0[i].z * x0[i].z + x0[i].w * x0[i].w
                 + x1[i].x * x1[i].x + x1[i].y * x1[i].y + x1[i].z * x1[i].z + x1[i].w * x1[i].w
                 + x2[i].x * x2[i].x + x2[i].y * x2[i].y + x2[i].z * x2[i].z + x2[i].w * x2[i].w;
        #pragma unroll
        for (int o = 16; o > 0; o >>= 1) ss += __shfl_xor_sync(0xffffffffu, ss, o);
        float invn = 1.0f / fmaxf(sqrtf(ss), EPSN);
        cls[i]  = g_cls[s];
        bfac[i] = cls[i] ? invn : 0.0f;
        float a = cls[i] ? invn * (g_counts[s] / maxden) : 0.0f;
        a0.x += x0[i].x * a; a0.y += x0[i].y * a; a0.z += x0[i].z * a; a0.w += x0[i].w * a;
        a1.x += x1[i].x * a; a1.y += x1[i].y * a; a1.z += x1[i].z * a; a1.w += x1[i].w * a;
        a2.x += x2[i].x * a; a2.y += x2[i].y * a; a2.z += x2[i].z * a; a2.w += x2[i].w * a;
    }
    atomicAdd(&s_v[4 * lane + 0], a0.x); atomicAdd(&s_v[4 * lane + 1], a0.y);
    atomicAdd(&s_v[4 * lane + 2], a0.z); atomicAdd(&s_v[4 * lane + 3], a0.w);
    atomicAdd(&s_v[128 + 4 * lane + 0], a1.x); atomicAdd(&s_v[128 + 4 * lane + 1], a1.y);
    atomicAdd(&s_v[128 + 4 * lane + 2], a1.z); atomicAdd(&s_v[128 + 4 * lane + 3], a1.w);
    if (lane < 16) {
        atomicAdd(&s_v[256 + 4 * lane + 0], a2.x); atomicAdd(&s_v[256 + 4 * lane + 1], a2.y);
        atomicAdd(&s_v[256 + 4 * lane + 2], a2.z); atomicAdd(&s_v[256 + 4 * lane + 3], a2.w);
    }
    __syncthreads();
    if (tid < DD) g_vpart[blockIdx.x * DD + tid] = s_v[tid];

    gridbar(0);

    // sliced v-reduction: this block owns column(s) blockIdx.x (+256)
    {
        int grp = tid >> 8;                       // 0 or 1
        int c   = blockIdx.x + grp * 256;
        if (c < DD) {
            int p = tid & 255;
            float v = __ldcg(&g_vpart[p * DD + c]);
            #pragma unroll
            for (int o = 16; o > 0; o >>= 1) v += __shfl_xor_sync(0xffffffffu, v, o);
            if (lane == 0) s_red[warp] = v;
        }
        __syncthreads();
        if (tid < DD && (tid & 255) == 0) {
            float v = 0.0f;
            int w0 = (tid >> 8) * 8;
            #pragma unroll
            for (int w = 0; w < 8; ++w) v += s_red[w0 + w];
            g_v[blockIdx.x + (tid >> 8) * 256] = v;
        }
    }

    gridbar(1);

    if (tid < DD) s_v[tid] = __ldcg(&g_v[tid]);
    __syncthreads();

    const float4* v4 = (const float4*)s_v;
    float4 v0 = v4[lane];
    float4 v1 = v4[32 + lane];
    float4 v2 = (lane < 16) ? v4[64 + lane] : z4;

    float sim[RPW];
    float psum = 0.0f, pcnt = 0.0f;
    #pragma unroll
    for (int i = 0; i < RPW; ++i) {
        float dot = x0[i].x * v0.x + x0[i].y * v0.y + x0[i].z * v0.z + x0[i].w * v0.w
                  + x1[i].x * v1.x + x1[i].y * v1.y + x1[i].z * v1.z + x1[i].w * v1.w
                  + x2[i].x * v2.x + x2[i].y * v2.y + x2[i].z * v2.z + x2[i].w * v2.w;
        #pragma unroll
        for (int o = 16; o > 0; o >>= 1) dot += __shfl_xor_sync(0xffffffffu, dot, o);
        sim[i] = bfac[i] * dot;
        if (lane == 0) {
            out_sim[base + i] = sim[i];
            if (cls[i]) { psum += sim[i]; pcnt += 1.0f; }
        }
    }
    if (lane == 0) { s_ms[warp] = psum; s_mc[warp] = pcnt; }
    __syncthreads();
    if (tid == 0) {
        float bs = 0.0f, bc = 0.0f;
        #pragma unroll
        for (int w = 0; w < 16; ++w) { bs += s_ms[w]; bc += s_mc[w]; }
        g_msum_p[blockIdx.x] = bs;
        g_mcnt_p[blockIdx.x] = bc;
    }

    gridbar(2);

    if (warp == 0) {
        float bs = 0.0f, bc = 0.0f;
        #pragma unroll
        for (int j = 0; j < FBLK / 32; ++j) {
            bs += *(volatile float*)&g_msum_p[lane + 32 * j];
            bc += *(volatile float*)&g_mcnt_p[lane + 32 * j];
        }
        #pragma unroll
        for (int o = 16; o > 0; o >>= 1) {
            bs += __shfl_xor_sync(0xffffffffu, bs, o);
            bc += __shfl_xor_sync(0xffffffffu, bc, o);
        }
        if (lane == 0) s_mean = bs / fmaxf(bc, 1.0f);
    }
    __syncthreads();
    float mean = s_mean;
    if (lane == 0) {
        #pragma unroll
        for (int i = 0; i < RPW; ++i)
            out_clean[base + i] = ((sim[i] > mean) && cls[i]) ? 1.0f : 0.0f;
    }
}

// ---------------- launch ----------------
extern "C" void kernel_launch(void* const* d_in, const int* in_sizes, int n_in,
                              void* d_out, int out_size) {
    const float* feat  = (const float*)d_in[0];
    const float* label = (const float*)d_in[1];
    const int*   clab  = (const int*)d_in[2];
    float* out = (float*)d_out;
    float* out_cm    = out;
    float* out_sim   = out + (size_t)SS * DD;
    float* out_clean = out + (size_t)SS * DD + SS;

    k_counts<<<KK, 512>>>(label, clab);
    k_gather<<<KK * GPC, 512>>>(feat, out_cm);
    k_fused<<<FBLK, FTPB>>>(out_cm, out_sim, out_clean);
}

// round 15
// speedup vs baseline: 1.1204x; 1.1204x over previous
#include <cuda_runtime.h>
#include <cuda_bf16.h>
#include <math.h>

#define KK   64
#define DD   320
#define NN   2048
#define MM   128
#define SS   (KK * MM)        // 8192
#define DB   4                // dims per gather block (contiguous chunk)
#define NB   (DD / DB)        // 80
#define EPSN 1e-12f
#define FBLK 256              // fused blocks, 2 per SM, all co-resident
#define FTPB 512              // 16 warps
#define RPW  2                // rows per warp: 256*16*2 = 8192

// swizzled transposed-feat index (bankgroup-permutation, proven in R8/R12)
#define SWIZ(p) (((p) & ~3) | (((p) + ((p) >> 3)) & 3))

// ---------------- device scratch ----------------
__device__ int   g_perm[KK * NN];        // sorted point index per cloud
__device__ int   g_off[SS];              // per-cloud exclusive prefix of counts
__device__ float g_counts[SS];
__device__ int   g_cls[SS];
__device__ float g_blkmax[KK];
__device__ float g_vpart[FBLK * DD];
__device__ float g_v[DD];
__device__ float g_msum_p[FBLK];
__device__ float g_mcnt_p[FBLK];
// tree barrier state: monotonic round counters (graph-replay safe)
__device__ int   g_leaf[3][16];
__device__ int   g_root[3];
__device__ int   g_flag[3];

// two-level grid barrier: 256 blocks -> 16 leaves -> root -> flag
__device__ __forceinline__ void gridbar(int which) {
    __syncthreads();
    if (threadIdx.x == 0) {
        __threadfence();
        int arr = atomicAdd(&g_leaf[which][blockIdx.x & 15], 1);
        int round = arr >> 4;              // 16 arrivals per leaf per round
        if ((arr & 15) == 15) {            // last of this leaf's round
            int ra = atomicAdd(&g_root[which], 1);
            if ((ra & 15) == 15) {         // last leaf of the round
                __threadfence();
                g_flag[which] = (ra >> 4) + 1;
            }
        }
        while (*(volatile int*)&g_flag[which] < round + 1) __nanosleep(32);
        __threadfence();
    }
    __syncthreads();
}

// ---------------- A: counts (4 sub-histograms) / offsets / perm / blockmax --
__global__ __launch_bounds__(512)
void k_counts(const float* __restrict__ label,
              const int*   __restrict__ clab) {
    __shared__ float s_cnt4[4][MM];
    __shared__ float s_lbl4[4][MM];
    __shared__ float s_cnt[MM];
    __shared__ float s_lbl[MM];
    __shared__ int   s_off[MM];
    __shared__ int   s_cur[MM];
    __shared__ float s_size[MM];
    int k = blockIdx.x;
    int tid = threadIdx.x;
    int lane = tid & 31;
    int h   = tid >> 7;                    // sub-histogram 0..3
    if (tid < MM) {
        #pragma unroll
        for (int j = 0; j < 4; ++j) { s_cnt4[j][tid] = 0.0f; s_lbl4[j][tid] = 0.0f; }
    }
    __syncthreads();
    const int base = k * NN;
    int4   c4 = ((const int4*)(clab + base))[tid];
    float4 l4 = ((const float4*)(label + base))[tid];
    atomicAdd(&s_cnt4[h][c4.x], 1.0f); atomicAdd(&s_lbl4[h][c4.x], l4.x);
    atomicAdd(&s_cnt4[h][c4.y], 1.0f); atomicAdd(&s_lbl4[h][c4.y], l4.y);
    atomicAdd(&s_cnt4[h][c4.z], 1.0f); atomicAdd(&s_lbl4[h][c4.z], l4.z);
    atomicAdd(&s_cnt4[h][c4.w], 1.0f); atomicAdd(&s_lbl4[h][c4.w], l4.w);
    __syncthreads();
    if (tid < MM) {
        s_cnt[tid] = (s_cnt4[0][tid] + s_cnt4[1][tid]) + (s_cnt4[2][tid] + s_cnt4[3][tid]);
        s_lbl[tid] = (s_lbl4[0][tid] + s_lbl4[1][tid]) + (s_lbl4[2][tid] + s_lbl4[3][tid]);
    }
    __syncthreads();
    if (tid < 32) {   // warp exclusive scan of 128 counts
        int e0 = (int)s_cnt[lane * 4 + 0];
        int e1 = (int)s_cnt[lane * 4 + 1];
        int e2 = (int)s_cnt[lane * 4 + 2];
        int e3 = (int)s_cnt[lane * 4 + 3];
        int t  = e0 + e1 + e2 + e3;
        int pre = t;
        #pragma unroll
        for (int o = 1; o < 32; o <<= 1) {
            int nb = __shfl_up_sync(0xffffffffu, pre, o);
            if (lane >= o) pre += nb;
        }
        int ex = pre - t;
        s_off[lane * 4 + 0] = ex;
        s_off[lane * 4 + 1] = ex + e0;
        s_off[lane * 4 + 2] = ex + e0 + e1;
        s_off[lane * 4 + 3] = ex + e0 + e1 + e2;
    }
    __syncthreads();
    if (tid < MM) {
        int s = k * MM + tid;
        float c  = s_cnt[tid];
        float dn = fmaxf(c, 1.0f);
        float lm = s_lbl[tid] / dn;
        int cls  = (lm > 0.5f) && (c > 0.0f);
        g_counts[s] = c;
        g_cls[s]    = cls;
        g_off[s]    = s_off[tid];
        s_cur[tid]  = s_off[tid];
        s_size[tid] = cls ? c : 0.0f;
    }
    __syncthreads();
    if (tid < 32) {   // per-cloud max size (plain store)
        float m = fmaxf(fmaxf(s_size[lane], s_size[lane + 32]),
                        fmaxf(s_size[lane + 64], s_size[lane + 96]));
        #pragma unroll
        for (int o = 16; o > 0; o >>= 1)
            m = fmaxf(m, __shfl_xor_sync(0xffffffffu, m, o));
        if (lane == 0) g_blkmax[k] = m;
    }
    {
        int n0 = tid * 4;
        int p;
        p = atomicAdd(&s_cur[c4.x], 1); g_perm[base + p] = n0 + 0;
        p = atomicAdd(&s_cur[c4.y], 1); g_perm[base + p] = n0 + 1;
        p = atomicAdd(&s_cur[c4.z], 1); g_perm[base + p] = n0 + 2;
        p = atomicAdd(&s_cur[c4.w], 1); g_perm[base + p] = n0 + 3;
    }
}

// ---------------- B: staged gather (quad-split + shuffle combine) -----------
// Thread (c = tid>>2, q = tid&3): quarter of cluster c's points; the 4
// partials live in adjacent lanes -> butterfly-shuffle combine (no s_red).
__global__ __launch_bounds__(512)
void k_gather(const float* __restrict__ feat,
              float*       __restrict__ out_cm) {
    __shared__ __align__(16) float4 s_ft[NN];             // 32 KB, [SWIZ(pt)]
    __shared__ __align__(16) int    s_perm[NN];           // 8 KB
    __shared__ int   s_off[MM + 1];
    int k     = blockIdx.x / NB;
    int dbase = (blockIdx.x % NB) * DB;
    int tid   = threadIdx.x;

    ((int4*)s_perm)[tid] = ((const int4*)(g_perm + k * NN))[tid];
    if (tid < MM) s_off[tid] = g_off[k * MM + tid];
    if (tid == 0) s_off[MM] = NN;

    // coalesced loads of the 4 dim-rows at column tid, register transpose,
    // swizzled STS.128 (bankgroup-perfect)
    const float* fb = feat + ((size_t)k * DD + dbase) * NN;
    float4 r0 = ((const float4*)(fb + 0 * NN))[tid];
    float4 r1 = ((const float4*)(fb + 1 * NN))[tid];
    float4 r2 = ((const float4*)(fb + 2 * NN))[tid];
    float4 r3 = ((const float4*)(fb + 3 * NN))[tid];
    int b  = 4 * tid;
    int sw = (tid >> 1) & 3;
    s_ft[b + ((0 + sw) & 3)] = make_float4(r0.x, r1.x, r2.x, r3.x);
    s_ft[b + ((1 + sw) & 3)] = make_float4(r0.y, r1.y, r2.y, r3.y);
    s_ft[b + ((2 + sw) & 3)] = make_float4(r0.z, r1.z, r2.z, r3.z);
    s_ft[b + ((3 + sw) & 3)] = make_float4(r0.w, r1.w, r2.w, r3.w);
    __syncthreads();

    int c = tid >> 2;                 // cluster 0..127
    int q = tid & 3;                  // quarter 0..3 (adjacent lanes)
    int st = s_off[c];
    int en = s_off[c + 1];
    float a0 = 0.f, a1 = 0.f, a2 = 0.f, a3 = 0.f;
    for (int p = st + q; p < en; p += 4) {
        float4 f = s_ft[SWIZ(s_perm[p])];
        a0 += f.x; a1 += f.y; a2 += f.z; a3 += f.w;
    }
    // combine quad partials via shuffles (deterministic order)
    a0 += __shfl_down_sync(0xffffffffu, a0, 2);
    a1 += __shfl_down_sync(0xffffffffu, a1, 2);
    a2 += __shfl_down_sync(0xffffffffu, a2, 2);
    a3 += __shfl_down_sync(0xffffffffu, a3, 2);
    a0 += __shfl_down_sync(0xffffffffu, a0, 1);
    a1 += __shfl_down_sync(0xffffffffu, a1, 1);
    a2 += __shfl_down_sync(0xffffffffu, a2, 1);
    a3 += __shfl_down_sync(0xffffffffu, a3, 1);
    if (q == 0) {
        int s = k * MM + c;
        float dn = 1.0f / fmaxf(g_counts[s], 1.0f);
        float4 o = make_float4(a0 * dn, a1 * dn, a2 * dn, a3 * dn);
        *(float4*)(out_cm + (size_t)s * DD + dbase) = o;
    }
}

// ---------------- F: fused norms + v + sim + mean + clean (R11/R12) ---------
__global__ void __launch_bounds__(FTPB, 2)
k_fused(const float* __restrict__ cm,
        float* __restrict__ out_sim,
        float* __restrict__ out_clean) {
    __shared__ __align__(16) float s_v[DD];
    __shared__ float s_ms[16];
    __shared__ float s_mc[16];
    __shared__ float s_md;
    __shared__ float s_mean;
    __shared__ float s_red[32];
    int tid  = threadIdx.x;
    int warp = tid >> 5;
    int lane = tid & 31;
    const float4 z4 = make_float4(0.f, 0.f, 0.f, 0.f);

    if (tid < DD) s_v[tid] = 0.0f;
    if (warp == 0) {   // maxden from per-cloud maxes
        float m = fmaxf(g_blkmax[lane], g_blkmax[lane + 32]);
        #pragma unroll
        for (int o = 16; o > 0; o >>= 1)
            m = fmaxf(m, __shfl_xor_sync(0xffffffffu, m, o));
        if (lane == 0) s_md = fmaxf(m, 1.0f);
    }

    const int base = blockIdx.x * (16 * RPW) + warp * RPW;

    float4 x0[RPW], x1[RPW], x2[RPW];
    #pragma unroll
    for (int i = 0; i < RPW; ++i) {
        const float4* rp = (const float4*)(cm + (size_t)(base + i) * DD);
        x0[i] = rp[lane];
        x1[i] = rp[32 + lane];
        x2[i] = (lane < 16) ? rp[64 + lane] : z4;
    }
    __syncthreads();
    float maxden = s_md;

    float bfac[RPW];
    int   cls[RPW];
    float4 a0 = z4, a1 = z4, a2 = z4;
    #pragma unroll
    for (int i = 0; i < RPW; ++i) {
        int s = base + i;
        float ss = x0[i].x * x0[i].x + x0[i].y * x0[i].y + x0[i].z * x0[i].z + x0[i].w * x0[i].w
                 + x1[i].x * x1[i].x + x1[i].y * x1[i].y + x1[i].z * x1[i].z + x1[i].w * x1[i].w
                 + x2[i].x * x2[i].x + x2[i].y * x2[i].y + x2[i].z * x2[i].z + x2[i].w * x2[i].w;
        #pragma unroll
        for (int o = 16; o > 0; o >>= 1) ss += __shfl_xor_sync(0xffffffffu, ss, o);
        float invn = 1.0f / fmaxf(sqrtf(ss), EPSN);
        cls[i]  = g_cls[s];
        bfac[i] = cls[i] ? invn : 0.0f;
        float a = cls[i] ? invn * (g_counts[s] / maxden) : 0.0f;
        a0.x += x0[i].x * a; a0.y += x0[i].y * a; a0.z += x0[i].z * a; a0.w += x0[i].w * a;
        a1.x += x1[i].x * a; a1.y += x1[i].y * a; a1.z += x1[i].z * a; a1.w += x1[i].w * a;
        a2.x += x2[i].x * a; a2.y += x2[i].y * a; a2.z += x2[i].z * a; a2.w += x2[i].w * a;
    }
    atomicAdd(&s_v[4 * lane + 0], a0.x); atomicAdd(&s_v[4 * lane + 1], a0.y);
    atomicAdd(&s_v[4 * lane + 2], a0.z); atomicAdd(&s_v[4 * lane + 3], a0.w);
    atomicAdd(&s_v[128 + 4 * lane + 0], a1.x); atomicAdd(&s_v[128 + 4 * lane + 1], a1.y);
    atomicAdd(&s_v[128 + 4 * lane + 2], a1.z); atomicAdd(&s_v[128 + 4 * lane + 3], a1.w);
    if (lane < 16) {
        atomicAdd(&s_v[256 + 4 * lane + 0], a2.x); atomicAdd(&s_v[256 + 4 * lane + 1], a2.y);
        atomicAdd(&s_v[256 + 4 * lane + 2], a2.z); atomicAdd(&s_v[256 + 4 * lane + 3], a2.w);
    }
    __syncthreads();
    if (tid < DD) g_vpart[blockIdx.x * DD + tid] = s_v[tid];

    gridbar(0);

    // sliced v-reduction: this block owns column(s) blockIdx.x (+256)
    {
        int grp = tid >> 8;                       // 0 or 1
        int c   = blockIdx.x + grp * 256;
        if (c < DD) {
            int p = tid & 255;
            float v = __ldcg(&g_vpart[p * DD + c]);
            #pragma unroll
            for (int o = 16; o > 0; o >>= 1) v += __shfl_xor_sync(0xffffffffu, v, o);
            if (lane == 0) s_red[warp] = v;
        }
        __syncthreads();
        if (tid < DD && (tid & 255) == 0) {
            float v = 0.0f;
            int w0 = (tid >> 8) * 8;
            #pragma unroll
            for (int w = 0; w < 8; ++w) v += s_red[w0 + w];
            g_v[blockIdx.x + (tid >> 8) * 256] = v;
        }
    }

    gridbar(1);

    if (tid < DD) s_v[tid] = __ldcg(&g_v[tid]);
    __syncthreads();

    const float4* v4 = (const float4*)s_v;
    float4 v0 = v4[lane];
    float4 v1 = v4[32 + lane];
    float4 v2 = (lane < 16) ? v4[64 + lane] : z4;

    float sim[RPW];
    float psum = 0.0f, pcnt = 0.0f;
    #pragma unroll
    for (int i = 0; i < RPW; ++i) {
        float dot = x0[i].x * v0.x + x0[i].y * v0.y + x0[i].z * v0.z + x0[i].w * v0.w
                  + x1[i].x * v1.x + x1[i].y * v1.y + x1[i].z * v1.z + x1[i].w * v1.w
                  + x2[i].x * v2.x + x2[i].y * v2.y + x2[i].z * v2.z + x2[i].w * v2.w;
        #pragma unroll
        for (int o = 16; o > 0; o >>= 1) dot += __shfl_xor_sync(0xffffffffu, dot, o);
        sim[i] = bfac[i] * dot;
        if (lane == 0) {
            out_sim[base + i] = sim[i];
            if (cls[i]) { psum += sim[i]; pcnt += 1.0f; }
        }
    }
    if (lane == 0) { s_ms[warp] = psum; s_mc[warp] = pcnt; }
    __syncthreads();
    if (tid == 0) {
        float bs = 0.0f, bc = 0.0f;
        #pragma unroll
        for (int w = 0; w < 16; ++w) { bs += s_ms[w]; bc += s_mc[w]; }
        g_msum_p[blockIdx.x] = bs;
        g_mcnt_p[blockIdx.x] = bc;
    }

    gridbar(2);

    if (warp == 0) {
        float bs = 0.0f, bc = 0.0f;
        #pragma unroll
        for (int j = 0; j < FBLK / 32; ++j) {
            bs += *(volatile float*)&g_msum_p[lane + 32 * j];
            bc += *(volatile float*)&g_mcnt_p[lane + 32 * j];
        }
        #pragma unroll
        for (int o = 16; o > 0; o >>= 1) {
            bs += __shfl_xor_sync(0xffffffffu, bs, o);
            bc += __shfl_xor_sync(0xffffffffu, bc, o);
        }
        if (lane == 0) s_mean = bs / fmaxf(bc, 1.0f);
    }
    __syncthreads();
    float mean = s_mean;
    if (lane == 0) {
        #pragma unroll
        for (int i = 0; i < RPW; ++i)
            out_clean[base + i] = ((sim[i] > mean) && cls[i]) ? 1.0f : 0.0f;
    }
}

// ---------------- launch ----------------
extern "C" void kernel_launch(void* const* d_in, const int* in_sizes, int n_in,
                              void* d_out, int out_size) {
    const float* feat  = (const float*)d_in[0];
    const float* label = (const float*)d_in[1];
    const int*   clab  = (const int*)d_in[2];
    float* out = (float*)d_out;
    float* out_cm    = out;
    float* out_sim   = out + (size_t)SS * DD;
    float* out_clean = out + (size_t)SS * DD + SS;

    k_counts<<<KK, 512>>>(label, clab);
    k_gather<<<KK * NB, 512>>>(feat, out_cm);
    k_fused<<<FBLK, FTPB>>>(out_cm, out_sim, out_clean);
}

// round 16
// speedup vs baseline: 1.1523x; 1.0284x over previous
#include <cuda_runtime.h>
#include <cuda_bf16.h>
#include <math.h>

#define KK   64
#define DD   320
#define NN   2048
#define MM   128
#define SS   (KK * MM)        // 8192
#define DB   4                // dims per chunk (contiguous in feat)
#define NB   (DD / DB)        // 80 chunks per cloud
#define GPC  8                // gather blocks per cloud
#define CPB  (NB / GPC)       // 10 chunks per block
#define EPSN 1e-12f
#define FBLK 256              // fused blocks, 2 per SM, all co-resident
#define FTPB 512              // 16 warps
#define RPW  2                // rows per warp: 256*16*2 = 8192

// swizzled transposed-feat index (bankgroup-permutation, proven R8/R12/R15)
#define SWIZ(p) (((p) & ~3) | (((p) + ((p) >> 3)) & 3))

// ---------------- device scratch ----------------
__device__ int   g_perm[KK * NN];        // sorted point index per cloud
__device__ int   g_off[SS];              // per-cloud exclusive prefix of counts
__device__ float g_counts[SS];
__device__ int   g_cls[SS];
__device__ float g_blkmax[KK];
__device__ float g_vpart[FBLK * DD];
__device__ float g_v[DD];
__device__ float g_msum_p[FBLK];
__device__ float g_mcnt_p[FBLK];
// tree barrier state: monotonic round counters (graph-replay safe)
__device__ int   g_leaf[3][16];
__device__ int   g_root[3];
__device__ int   g_flag[3];

// two-level grid barrier: 256 blocks -> 16 leaves -> root -> flag
__device__ __forceinline__ void gridbar(int which) {
    __syncthreads();
    if (threadIdx.x == 0) {
        __threadfence();
        int arr = atomicAdd(&g_leaf[which][blockIdx.x & 15], 1);
        int round = arr >> 4;              // 16 arrivals per leaf per round
        if ((arr & 15) == 15) {            // last of this leaf's round
            int ra = atomicAdd(&g_root[which], 1);
            if ((ra & 15) == 15) {         // last leaf of the round
                __threadfence();
                g_flag[which] = (ra >> 4) + 1;
            }
        }
        while (*(volatile int*)&g_flag[which] < round + 1) __nanosleep(32);
        __threadfence();
    }
    __syncthreads();
}

// ---------------- A: counts (4 sub-histograms) / offsets / perm / blockmax --
__global__ __launch_bounds__(512)
void k_counts(const float* __restrict__ label,
              const int*   __restrict__ clab) {
    __shared__ float s_cnt4[4][MM];
    __shared__ float s_lbl4[4][MM];
    __shared__ float s_cnt[MM];
    __shared__ float s_lbl[MM];
    __shared__ int   s_off[MM];
    __shared__ int   s_cur[MM];
    __shared__ float s_size[MM];
    int k = blockIdx.x;
    int tid = threadIdx.x;
    int lane = tid & 31;
    int h   = tid >> 7;                    // sub-histogram 0..3
    if (tid < MM) {
        #pragma unroll
        for (int j = 0; j < 4; ++j) { s_cnt4[j][tid] = 0.0f; s_lbl4[j][tid] = 0.0f; }
    }
    __syncthreads();
    const int base = k * NN;
    int4   c4 = ((const int4*)(clab + base))[tid];
    float4 l4 = ((const float4*)(label + base))[tid];
    atomicAdd(&s_cnt4[h][c4.x], 1.0f); atomicAdd(&s_lbl4[h][c4.x], l4.x);
    atomicAdd(&s_cnt4[h][c4.y], 1.0f); atomicAdd(&s_lbl4[h][c4.y], l4.y);
    atomicAdd(&s_cnt4[h][c4.z], 1.0f); atomicAdd(&s_lbl4[h][c4.z], l4.z);
    atomicAdd(&s_cnt4[h][c4.w], 1.0f); atomicAdd(&s_lbl4[h][c4.w], l4.w);
    __syncthreads();
    if (tid < MM) {
        s_cnt[tid] = (s_cnt4[0][tid] + s_cnt4[1][tid]) + (s_cnt4[2][tid] + s_cnt4[3][tid]);
        s_lbl[tid] = (s_lbl4[0][tid] + s_lbl4[1][tid]) + (s_lbl4[2][tid] + s_lbl4[3][tid]);
    }
    __syncthreads();
    if (tid < 32) {   // warp exclusive scan of 128 counts
        int e0 = (int)s_cnt[lane * 4 + 0];
        int e1 = (int)s_cnt[lane * 4 + 1];
        int e2 = (int)s_cnt[lane * 4 + 2];
        int e3 = (int)s_cnt[lane * 4 + 3];
        int t  = e0 + e1 + e2 + e3;
        int pre = t;
        #pragma unroll
        for (int o = 1; o < 32; o <<= 1) {
            int nb = __shfl_up_sync(0xffffffffu, pre, o);
            if (lane >= o) pre += nb;
        }
        int ex = pre - t;
        s_off[lane * 4 + 0] = ex;
        s_off[lane * 4 + 1] = ex + e0;
        s_off[lane * 4 + 2] = ex + e0 + e1;
        s_off[lane * 4 + 3] = ex + e0 + e1 + e2;
    }
    __syncthreads();
    if (tid < MM) {
        int s = k * MM + tid;
        float c  = s_cnt[tid];
        float dn = fmaxf(c, 1.0f);
        float lm = s_lbl[tid] / dn;
        int cls  = (lm > 0.5f) && (c > 0.0f);
        g_counts[s] = c;
        g_cls[s]    = cls;
        g_off[s]    = s_off[tid];
        s_cur[tid]  = s_off[tid];
        s_size[tid] = cls ? c : 0.0f;
    }
    __syncthreads();
    if (tid < 32) {   // per-cloud max size (plain store)
        float m = fmaxf(fmaxf(s_size[lane], s_size[lane + 32]),
                        fmaxf(s_size[lane + 64], s_size[lane + 96]));
        #pragma unroll
        for (int o = 16; o > 0; o >>= 1)
            m = fmaxf(m, __shfl_xor_sync(0xffffffffu, m, o));
        if (lane == 0) g_blkmax[k] = m;
    }
    {
        int n0 = tid * 4;
        int p;
        p = atomicAdd(&s_cur[c4.x], 1); g_perm[base + p] = n0 + 0;
        p = atomicAdd(&s_cur[c4.y], 1); g_perm[base + p] = n0 + 1;
        p = atomicAdd(&s_cur[c4.z], 1); g_perm[base + p] = n0 + 2;
        p = atomicAdd(&s_cur[c4.w], 1); g_perm[base + p] = n0 + 3;
    }
}

// ---------------- B: multi-chunk gather, register-buffered pipeline ---------
// 512 blocks (4/SM, one wave), block (k, part) owns 10 chunks. Perm staged
// once. Loop: STS staged regs -> sync -> issue next chunk LDGs (fly during
// compute) -> quad-split compute + shuffle combine -> sync.
__global__ __launch_bounds__(512)
void k_gather(const float* __restrict__ feat,
              float*       __restrict__ out_cm) {
    __shared__ __align__(16) float4 s_ft[NN];             // 32 KB, [SWIZ(pt)]
    __shared__ __align__(16) int    s_perm[NN];           // 8 KB
    __shared__ int   s_off[MM + 1];
    int k    = blockIdx.x / GPC;
    int part = blockIdx.x % GPC;
    int tid  = threadIdx.x;

    ((int4*)s_perm)[tid] = ((const int4*)(g_perm + k * NN))[tid];
    if (tid < MM) s_off[tid] = g_off[k * MM + tid];
    if (tid == 0) s_off[MM] = NN;

    const float* fb0 = feat + (size_t)k * DD * NN + (size_t)(part * CPB) * DB * NN;

    // prologue: load chunk 0 into registers
    float4 r0 = ((const float4*)(fb0 + 0 * NN))[tid];
    float4 r1 = ((const float4*)(fb0 + 1 * NN))[tid];
    float4 r2 = ((const float4*)(fb0 + 2 * NN))[tid];
    float4 r3 = ((const float4*)(fb0 + 3 * NN))[tid];

    __syncthreads();                  // perm/off staged

    int c = tid >> 2;                 // cluster 0..127
    int q = tid & 3;                  // quarter 0..3 (adjacent lanes)
    int st = s_off[c];
    int en = s_off[c + 1];
    int b  = 4 * tid;
    int sw = (tid >> 1) & 3;
    float dn = 1.0f / fmaxf(g_counts[k * MM + c], 1.0f);

    for (int cc = 0; cc < CPB; ++cc) {
        // store current chunk (swizzled transposed STS.128)
        s_ft[b + ((0 + sw) & 3)] = make_float4(r0.x, r1.x, r2.x, r3.x);
        s_ft[b + ((1 + sw) & 3)] = make_float4(r0.y, r1.y, r2.y, r3.y);
        s_ft[b + ((2 + sw) & 3)] = make_float4(r0.z, r1.z, r2.z, r3.z);
        s_ft[b + ((3 + sw) & 3)] = make_float4(r0.w, r1.w, r2.w, r3.w);
        __syncthreads();

        // issue next chunk's loads; they fly while we compute
        if (cc + 1 < CPB) {
            const float* fb = fb0 + (size_t)(cc + 1) * DB * NN;
            r0 = ((const float4*)(fb + 0 * NN))[tid];
            r1 = ((const float4*)(fb + 1 * NN))[tid];
            r2 = ((const float4*)(fb + 2 * NN))[tid];
            r3 = ((const float4*)(fb + 3 * NN))[tid];
        }

        float a0 = 0.f, a1 = 0.f, a2 = 0.f, a3 = 0.f;
        for (int p = st + q; p < en; p += 4) {
            float4 f = s_ft[SWIZ(s_perm[p])];
            a0 += f.x; a1 += f.y; a2 += f.z; a3 += f.w;
        }
        a0 += __shfl_down_sync(0xffffffffu, a0, 2);
        a1 += __shfl_down_sync(0xffffffffu, a1, 2);
        a2 += __shfl_down_sync(0xffffffffu, a2, 2);
        a3 += __shfl_down_sync(0xffffffffu, a3, 2);
        a0 += __shfl_down_sync(0xffffffffu, a0, 1);
        a1 += __shfl_down_sync(0xffffffffu, a1, 1);
        a2 += __shfl_down_sync(0xffffffffu, a2, 1);
        a3 += __shfl_down_sync(0xffffffffu, a3, 1);
        if (q == 0) {
            int s = k * MM + c;
            int dbase = (part * CPB + cc) * DB;
            float4 o = make_float4(a0 * dn, a1 * dn, a2 * dn, a3 * dn);
            *(float4*)(out_cm + (size_t)s * DD + dbase) = o;
        }
        __syncthreads();              // all reads of s_ft done before next STS
    }
}

// ---------------- F: fused norms + v + sim + mean + clean (R11/R12) ---------
__global__ void __launch_bounds__(FTPB, 2)
k_fused(const float* __restrict__ cm,
        float* __restrict__ out_sim,
        float* __restrict__ out_clean) {
    __shared__ __align__(16) float s_v[DD];
    __shared__ float s_ms[16];
    __shared__ float s_mc[16];
    __shared__ float s_md;
    __shared__ float s_mean;
    __shared__ float s_red[32];
    int tid  = threadIdx.x;
    int warp = tid >> 5;
    int lane = tid & 31;
    const float4 z4 = make_float4(0.f, 0.f, 0.f, 0.f);

    if (tid < DD) s_v[tid] = 0.0f;
    if (warp == 0) {   // maxden from per-cloud maxes
        float m = fmaxf(g_blkmax[lane], g_blkmax[lane + 32]);
        #pragma unroll
        for (int o = 16; o > 0; o >>= 1)
            m = fmaxf(m, __shfl_xor_sync(0xffffffffu, m, o));
        if (lane == 0) s_md = fmaxf(m, 1.0f);
    }

    const int base = blockIdx.x * (16 * RPW) + warp * RPW;

    float4 x0[RPW], x1[RPW], x2[RPW];
    #pragma unroll
    for (int i = 0; i < RPW; ++i) {
        const float4* rp = (const float4*)(cm + (size_t)(base + i) * DD);
        x0[i] = rp[lane];
        x1[i] = rp[32 + lane];
        x2[i] = (lane < 16) ? rp[64 + lane] : z4;
    }
    __syncthreads();
    float maxden = s_md;

    float bfac[RPW];
    int   cls[RPW];
    float4 a0 = z4, a1 = z4, a2 = z4;
    #pragma unroll
    for (int i = 0; i < RPW; ++i) {
        int s = base + i;
        float ss = x0[i].x * x0[i].x + x0[i].y * x0[i].y + x0[i].z * x0[i].z + x0[i].w * x0[i].w
                 + x1[i].x * x1[i].x + x1[i].y * x1[i].y + x1[i].z * x1[i].z + x1[i].w * x1[i].w
                 + x2[i].x * x2[i].x + x2[i].y * x2[i].y + x2[i].z * x2[i].z + x2[i].w * x2[i].w;
        #pragma unroll
        for (int o = 16; o > 0; o >>= 1) ss += __shfl_xor_sync(0xffffffffu, ss, o);
        float invn = 1.0f / fmaxf(sqrtf(ss), EPSN);
        cls[i]  = g_cls[s];
        bfac[i] = cls[i] ? invn : 0.0f;
        float a = cls[i] ? invn * (g_counts[s] / maxden) : 0.0f;
        a0.x += x0[i].x * a; a0.y += x0[i].y * a; a0.z += x0[i].z * a; a0.w += x0[i].w * a;
        a1.x += x1[i].x * a; a1.y += x1[i].y * a; a1.z += x1[i].z * a; a1.w += x1[i].w * a;
        a2.x += x2[i].x * a; a2.y += x2[i].y * a; a2.z += x2[i].z * a; a2.w += x2[i].w * a;
    }
    atomicAdd(&s_v[4 * lane + 0], a0.x); atomicAdd(&s_v[4 * lane + 1], a0.y);
    atomicAdd(&s_v[4 * lane + 2], a0.z); atomicAdd(&s_v[4 * lane + 3], a0.w);
    atomicAdd(&s_v[128 + 4 * lane + 0], a1.x); atomicAdd(&s_v[128 + 4 * lane + 1], a1.y);
    atomicAdd(&s_v[128 + 4 * lane + 2], a1.z); atomicAdd(&s_v[128 + 4 * lane + 3], a1.w);
    if (lane < 16) {
        atomicAdd(&s_v[256 + 4 * lane + 0], a2.x); atomicAdd(&s_v[256 + 4 * lane + 1], a2.y);
        atomicAdd(&s_v[256 + 4 * lane + 2], a2.z); atomicAdd(&s_v[256 + 4 * lane + 3], a2.w);
    }
    __syncthreads();
    if (tid < DD) g_vpart[blockIdx.x * DD + tid] = s_v[tid];

    gridbar(0);

    // sliced v-reduction: this block owns column(s) blockIdx.x (+256)
    {
        int grp = tid >> 8;                       // 0 or 1
        int c   = blockIdx.x + grp * 256;
        if (c < DD) {
            int p = tid & 255;
            float v = __ldcg(&g_vpart[p * DD + c]);
            #pragma unroll
            for (int o = 16; o > 0; o >>= 1) v += __shfl_xor_sync(0xffffffffu, v, o);
            if (lane == 0) s_red[warp] = v;
        }
        __syncthreads();
        if (tid < DD && (tid & 255) == 0) {
            float v = 0.0f;
            int w0 = (tid >> 8) * 8;
            #pragma unroll
            for (int w = 0; w < 8; ++w) v += s_red[w0 + w];
            g_v[blockIdx.x + (tid >> 8) * 256] = v;
        }
    }

    gridbar(1);

    if (tid < DD) s_v[tid] = __ldcg(&g_v[tid]);
    __syncthreads();

    const float4* v4 = (const float4*)s_v;
    float4 v0 = v4[lane];
    float4 v1 = v4[32 + lane];
    float4 v2 = (lane < 16) ? v4[64 + lane] : z4;

    float sim[RPW];
    float psum = 0.0f, pcnt = 0.0f;
    #pragma unroll
    for (int i = 0; i < RPW; ++i) {
        float dot = x0[i].x * v0.x + x0[i].y * v0.y + x0[i].z * v0.z + x0[i].w * v0.w
                  + x1[i].x * v1.x + x1[i].y * v1.y + x1[i].z * v1.z + x1[i].w * v1.w
                  + x2[i].x * v2.x + x2[i].y * v2.y + x2[i].z * v2.z + x2[i].w * v2.w;
        #pragma unroll
        for (int o = 16; o > 0; o >>= 1) dot += __shfl_xor_sync(0xffffffffu, dot, o);
        sim[i] = bfac[i] * dot;
        if (lane == 0) {
            out_sim[base + i] = sim[i];
            if (cls[i]) { psum += sim[i]; pcnt += 1.0f; }
        }
    }
    if (lane == 0) { s_ms[warp] = psum; s_mc[warp] = pcnt; }
    __syncthreads();
    if (tid == 0) {
        float bs = 0.0f, bc = 0.0f;
        #pragma unroll
        for (int w = 0; w < 16; ++w) { bs += s_ms[w]; bc += s_mc[w]; }
        g_msum_p[blockIdx.x] = bs;
        g_mcnt_p[blockIdx.x] = bc;
    }

    gridbar(2);

    if (warp == 0) {
        float bs = 0.0f, bc = 0.0f;
        #pragma unroll
        for (int j = 0; j < FBLK / 32; ++j) {
            bs += *(volatile float*)&g_msum_p[lane + 32 * j];
            bc += *(volatile float*)&g_mcnt_p[lane + 32 * j];
        }
        #pragma unroll
        for (int o = 16; o > 0; o >>= 1) {
            bs += __shfl_xor_sync(0xffffffffu, bs, o);
            bc += __shfl_xor_sync(0xffffffffu, bc, o);
        }
        if (lane == 0) s_mean = bs / fmaxf(bc, 1.0f);
    }
    __syncthreads();
    float mean = s_mean;
    if (lane == 0) {
        #pragma unroll
        for (int i = 0; i < RPW; ++i)
            out_clean[base + i] = ((sim[i] > mean) && cls[i]) ? 1.0f : 0.0f;
    }
}

// ---------------- launch ----------------
extern "C" void kernel_launch(void* const* d_in, const int* in_sizes, int n_in,
                              void* d_out, int out_size) {
    const float* feat  = (const float*)d_in[0];
    const float* label = (const float*)d_in[1];
    const int*   clab  = (const int*)d_in[2];
    float* out = (float*)d_out;
    float* out_cm    = out;
    float* out_sim   = out + (size_t)SS * DD;
    float* out_clean = out + (size_t)SS * DD + SS;

    k_counts<<<KK, 512>>>(label, clab);
    k_gather<<<KK * GPC, 512>>>(feat, out_cm);
    k_fused<<<FBLK, FTPB>>>(out_cm, out_sim, out_clean);
}

// round 17
// speedup vs baseline: 1.1760x; 1.0206x over previous
#include <cuda_runtime.h>
#include <cuda_bf16.h>
#include <math.h>

#define KK   64
#define DD   320
#define NN   2048
#define MM   128
#define SS   (KK * MM)        // 8192
#define DB   4                // dims per chunk (contiguous in feat)
#define NB   (DD / DB)        // 80 chunks per cloud
#define GPC  16               // work units per cloud
#define CPB  (NB / GPC)       // 5 chunks per unit
#define NUNITS (KK * GPC)     // 1024 units
#define GBLK 444              // persistent gather blocks (148 SMs x 3)
#define EPSN 1e-12f
#define FBLK 256              // fused blocks, 2 per SM, all co-resident
#define FTPB 512              // 16 warps
#define RPW  2                // rows per warp: 256*16*2 = 8192

// swizzled transposed-feat index (bankgroup-permutation, proven R8/R12/R15)
#define SWIZ(p) (((p) & ~3) | (((p) + ((p) >> 3)) & 3))

// ---------------- device scratch ----------------
__device__ int   g_perm[KK * NN];        // sorted point index per cloud
__device__ int   g_off[SS];              // per-cloud exclusive prefix of counts
__device__ float g_counts[SS];
__device__ int   g_cls[SS];
__device__ float g_blkmax[KK];
__device__ float g_vpart[FBLK * DD];
__device__ float g_v[DD];
__device__ float g_msum_p[FBLK];
__device__ float g_mcnt_p[FBLK];
__device__ int   g_queue;                // gather work queue (reset by k_counts)
// tree barrier state: monotonic round counters (graph-replay safe)
__device__ int   g_leaf[3][16];
__device__ int   g_root[3];
__device__ int   g_flag[3];

// two-level grid barrier: 256 blocks -> 16 leaves -> root -> flag
__device__ __forceinline__ void gridbar(int which) {
    __syncthreads();
    if (threadIdx.x == 0) {
        __threadfence();
        int arr = atomicAdd(&g_leaf[which][blockIdx.x & 15], 1);
        int round = arr >> 4;              // 16 arrivals per leaf per round
        if ((arr & 15) == 15) {            // last of this leaf's round
            int ra = atomicAdd(&g_root[which], 1);
            if ((ra & 15) == 15) {         // last leaf of the round
                __threadfence();
                g_flag[which] = (ra >> 4) + 1;
            }
        }
        while (*(volatile int*)&g_flag[which] < round + 1) __nanosleep(32);
        __threadfence();
    }
    __syncthreads();
}

// ---------------- A: counts (1024 thr) / offsets / perm / blockmax / queue --
__global__ __launch_bounds__(1024)
void k_counts(const float* __restrict__ label,
              const int*   __restrict__ clab) {
    __shared__ float s_cnt4[4][MM];
    __shared__ float s_lbl4[4][MM];
    __shared__ float s_cnt[MM];
    __shared__ float s_lbl[MM];
    __shared__ int   s_off[MM];
    __shared__ int   s_cur[MM];
    __shared__ float s_size[MM];
    int k = blockIdx.x;
    int tid = threadIdx.x;
    int lane = tid & 31;
    int h   = tid >> 8;                    // sub-histogram 0..3
    if (k == 0 && tid == 0) g_queue = 0;   // reset gather work queue (graph-safe)
    if (tid < MM) {
        #pragma unroll
        for (int j = 0; j < 4; ++j) { s_cnt4[j][tid] = 0.0f; s_lbl4[j][tid] = 0.0f; }
    }
    __syncthreads();
    const int base = k * NN;
    int2   c2 = ((const int2*)(clab + base))[tid];
    float2 l2 = ((const float2*)(label + base))[tid];
    atomicAdd(&s_cnt4[h][c2.x], 1.0f); atomicAdd(&s_lbl4[h][c2.x], l2.x);
    atomicAdd(&s_cnt4[h][c2.y], 1.0f); atomicAdd(&s_lbl4[h][c2.y], l2.y);
    __syncthreads();
    if (tid < MM) {
        s_cnt[tid] = (s_cnt4[0][tid] + s_cnt4[1][tid]) + (s_cnt4[2][tid] + s_cnt4[3][tid]);
        s_lbl[tid] = (s_lbl4[0][tid] + s_lbl4[1][tid]) + (s_lbl4[2][tid] + s_lbl4[3][tid]);
    }
    __syncthreads();
    if (tid < 32) {   // warp exclusive scan of 128 counts
        int e0 = (int)s_cnt[lane * 4 + 0];
        int e1 = (int)s_cnt[lane * 4 + 1];
        int e2 = (int)s_cnt[lane * 4 + 2];
        int e3 = (int)s_cnt[lane * 4 + 3];
        int t  = e0 + e1 + e2 + e3;
        int pre = t;
        #pragma unroll
        for (int o = 1; o < 32; o <<= 1) {
            int nb = __shfl_up_sync(0xffffffffu, pre, o);
            if (lane >= o) pre += nb;
        }
        int ex = pre - t;
        s_off[lane * 4 + 0] = ex;
        s_off[lane * 4 + 1] = ex + e0;
        s_off[lane * 4 + 2] = ex + e0 + e1;
        s_off[lane * 4 + 3] = ex + e0 + e1 + e2;
    }
    __syncthreads();
    if (tid < MM) {
        int s = k * MM + tid;
        float c  = s_cnt[tid];
        float dn = fmaxf(c, 1.0f);
        float lm = s_lbl[tid] / dn;
        int cls  = (lm > 0.5f) && (c > 0.0f);
        g_counts[s] = c;
        g_cls[s]    = cls;
        g_off[s]    = s_off[tid];
        s_cur[tid]  = s_off[tid];
        s_size[tid] = cls ? c : 0.0f;
    }
    __syncthreads();
    if (tid < 32) {   // per-cloud max size (plain store)
        float m = fmaxf(fmaxf(s_size[lane], s_size[lane + 32]),
                        fmaxf(s_size[lane + 64], s_size[lane + 96]));
        #pragma unroll
        for (int o = 16; o > 0; o >>= 1)
            m = fmaxf(m, __shfl_xor_sync(0xffffffffu, m, o));
        if (lane == 0) g_blkmax[k] = m;
    }
    {
        int n0 = tid * 2;
        int p;
        p = atomicAdd(&s_cur[c2.x], 1); g_perm[base + p] = n0 + 0;
        p = atomicAdd(&s_cur[c2.y], 1); g_perm[base + p] = n0 + 1;
    }
}

// ---------------- B: persistent work-queue gather ----------------
// 444 blocks (3/SM pinned). Units = (cloud, part) of 5 chunks; blocks pull
// from g_queue (zeroed by k_counts each replay). Register-staged pipeline +
// swizzled transposed tile (R16 mechanics).
__global__ void __launch_bounds__(512, 3)
k_gather(const float* __restrict__ feat,
         float*       __restrict__ out_cm) {
    __shared__ __align__(16) float4 s_ft[NN];             // 32 KB, [SWIZ(pt)]
    __shared__ __align__(16) int    s_perm[NN];           // 8 KB
    __shared__ int   s_off[MM + 1];
    __shared__ int   s_task;
    int tid = threadIdx.x;

    while (true) {
        if (tid == 0) s_task = atomicAdd(&g_queue, 1);
        __syncthreads();                  // broadcast task; also orders prior
        int t = s_task;                   // unit id
        if (t >= NUNITS) break;
        int k    = t / GPC;
        int part = t % GPC;

        ((int4*)s_perm)[tid] = ((const int4*)(g_perm + k * NN))[tid];
        if (tid < MM) s_off[tid] = g_off[k * MM + tid];
        if (tid == 0) s_off[MM] = NN;

        const float* fb0 = feat + (size_t)k * DD * NN + (size_t)(part * CPB) * DB * NN;

        // prologue: load chunk 0 into registers
        float4 r0 = ((const float4*)(fb0 + 0 * NN))[tid];
        float4 r1 = ((const float4*)(fb0 + 1 * NN))[tid];
        float4 r2 = ((const float4*)(fb0 + 2 * NN))[tid];
        float4 r3 = ((const float4*)(fb0 + 3 * NN))[tid];

        __syncthreads();                  // perm/off staged

        int c = tid >> 2;                 // cluster 0..127
        int q = tid & 3;                  // quarter 0..3 (adjacent lanes)
        int st = s_off[c];
        int en = s_off[c + 1];
        int b  = 4 * tid;
        int sw = (tid >> 1) & 3;
        float dn = 1.0f / fmaxf(g_counts[k * MM + c], 1.0f);

        for (int cc = 0; cc < CPB; ++cc) {
            // store current chunk (swizzled transposed STS.128)
            s_ft[b + ((0 + sw) & 3)] = make_float4(r0.x, r1.x, r2.x, r3.x);
            s_ft[b + ((1 + sw) & 3)] = make_float4(r0.y, r1.y, r2.y, r3.y);
            s_ft[b + ((2 + sw) & 3)] = make_float4(r0.z, r1.z, r2.z, r3.z);
            s_ft[b + ((3 + sw) & 3)] = make_float4(r0.w, r1.w, r2.w, r3.w);
            __syncthreads();

            // issue next chunk's loads; they fly while we compute
            if (cc + 1 < CPB) {
                const float* fb = fb0 + (size_t)(cc + 1) * DB * NN;
                r0 = ((const float4*)(fb + 0 * NN))[tid];
                r1 = ((const float4*)(fb + 1 * NN))[tid];
                r2 = ((const float4*)(fb + 2 * NN))[tid];
                r3 = ((const float4*)(fb + 3 * NN))[tid];
            }

            float a0 = 0.f, a1 = 0.f, a2 = 0.f, a3 = 0.f;
            for (int p = st + q; p < en; p += 4) {
                float4 f = s_ft[SWIZ(s_perm[p])];
                a0 += f.x; a1 += f.y; a2 += f.z; a3 += f.w;
            }
            a0 += __shfl_down_sync(0xffffffffu, a0, 2);
            a1 += __shfl_down_sync(0xffffffffu, a1, 2);
            a2 += __shfl_down_sync(0xffffffffu, a2, 2);
            a3 += __shfl_down_sync(0xffffffffu, a3, 2);
            a0 += __shfl_down_sync(0xffffffffu, a0, 1);
            a1 += __shfl_down_sync(0xffffffffu, a1, 1);
            a2 += __shfl_down_sync(0xffffffffu, a2, 1);
            a3 += __shfl_down_sync(0xffffffffu, a3, 1);
            if (q == 0) {
                int s = k * MM + c;
                int dbase = (part * CPB + cc) * DB;
                float4 o = make_float4(a0 * dn, a1 * dn, a2 * dn, a3 * dn);
                *(float4*)(out_cm + (size_t)s * DD + dbase) = o;
            }
            __syncthreads();          // s_ft reads done before next STS
        }
    }
}

// ---------------- F: fused norms + v + sim + mean + clean (R11/R12) ---------
__global__ void __launch_bounds__(FTPB, 2)
k_fused(const float* __restrict__ cm,
        float* __restrict__ out_sim,
        float* __restrict__ out_clean) {
    __shared__ __align__(16) float s_v[DD];
    __shared__ float s_ms[16];
    __shared__ float s_mc[16];
    __shared__ float s_md;
    __shared__ float s_mean;
    __shared__ float s_red[32];
    int tid  = threadIdx.x;
    int warp = tid >> 5;
    int lane = tid & 31;
    const float4 z4 = make_float4(0.f, 0.f, 0.f, 0.f);

    if (tid < DD) s_v[tid] = 0.0f;
    if (warp == 0) {   // maxden from per-cloud maxes
        float m = fmaxf(g_blkmax[lane], g_blkmax[lane + 32]);
        #pragma unroll
        for (int o = 16; o > 0; o >>= 1)
            m = fmaxf(m, __shfl_xor_sync(0xffffffffu, m, o));
        if (lane == 0) s_md = fmaxf(m, 1.0f);
    }

    const int base = blockIdx.x * (16 * RPW) + warp * RPW;

    float4 x0[RPW], x1[RPW], x2[RPW];
    #pragma unroll
    for (int i = 0; i < RPW; ++i) {
        const float4* rp = (const float4*)(cm + (size_t)(base + i) * DD);
        x0[i] = rp[lane];
        x1[i] = rp[32 + lane];
        x2[i] = (lane < 16) ? rp[64 + lane] : z4;
    }
    __syncthreads();
    float maxden = s_md;

    float bfac[RPW];
    int   cls[RPW];
    float4 a0 = z4, a1 = z4, a2 = z4;
    #pragma unroll
    for (int i = 0; i < RPW; ++i) {
        int s = base + i;
        float ss = x0[i].x * x0[i].x + x0[i].y * x0[i].y + x0[i].z * x0[i].z + x0[i].w * x0[i].w
                 + x1[i].x * x1[i].x + x1[i].y * x1[i].y + x1[i].z * x1[i].z + x1[i].w * x1[i].w
                 + x2[i].x * x2[i].x + x2[i].y * x2[i].y + x2[i].z * x2[i].z + x2[i].w * x2[i].w;
        #pragma unroll
        for (int o = 16; o > 0; o >>= 1) ss += __shfl_xor_sync(0xffffffffu, ss, o);
        float invn = 1.0f / fmaxf(sqrtf(ss), EPSN);
        cls[i]  = g_cls[s];
        bfac[i] = cls[i] ? invn : 0.0f;
        float a = cls[i] ? invn * (g_counts[s] / maxden) : 0.0f;
        a0.x += x0[i].x * a; a0.y += x0[i].y * a; a0.z += x0[i].z * a; a0.w += x0[i].w * a;
        a1.x += x1[i].x * a; a1.y += x1[i].y * a; a1.z += x1[i].z * a; a1.w += x1[i].w * a;
        a2.x += x2[i].x * a; a2.y += x2[i].y * a; a2.z += x2[i].z * a; a2.w += x2[i].w * a;
    }
    atomicAdd(&s_v[4 * lane + 0], a0.x); atomicAdd(&s_v[4 * lane + 1], a0.y);
    atomicAdd(&s_v[4 * lane + 2], a0.z); atomicAdd(&s_v[4 * lane + 3], a0.w);
    atomicAdd(&s_v[128 + 4 * lane + 0], a1.x); atomicAdd(&s_v[128 + 4 * lane + 1], a1.y);
    atomicAdd(&s_v[128 + 4 * lane + 2], a1.z); atomicAdd(&s_v[128 + 4 * lane + 3], a1.w);
    if (lane < 16) {
        atomicAdd(&s_v[256 + 4 * lane + 0], a2.x); atomicAdd(&s_v[256 + 4 * lane + 1], a2.y);
        atomicAdd(&s_v[256 + 4 * lane + 2], a2.z); atomicAdd(&s_v[256 + 4 * lane + 3], a2.w);
    }
    __syncthreads();
    if (tid < DD) g_vpart[blockIdx.x * DD + tid] = s_v[tid];

    gridbar(0);

    // sliced v-reduction: this block owns column(s) blockIdx.x (+256)
    {
        int grp = tid >> 8;                       // 0 or 1
        int c   = blockIdx.x + grp * 256;
        if (c < DD) {
            int p = tid & 255;
            float v = __ldcg(&g_vpart[p * DD + c]);
            #pragma unroll
            for (int o = 16; o > 0; o >>= 1) v += __shfl_xor_sync(0xffffffffu, v, o);
            if (lane == 0) s_red[warp] = v;
        }
        __syncthreads();
        if (tid < DD && (tid & 255) == 0) {
            float v = 0.0f;
            int w0 = (tid >> 8) * 8;
            #pragma unroll
            for (int w = 0; w < 8; ++w) v += s_red[w0 + w];
            g_v[blockIdx.x + (tid >> 8) * 256] = v;
        }
    }

    gridbar(1);

    if (tid < DD) s_v[tid] = __ldcg(&g_v[tid]);
    __syncthreads();

    const float4* v4 = (const float4*)s_v;
    float4 v0 = v4[lane];
    float4 v1 = v4[32 + lane];
    float4 v2 = (lane < 16) ? v4[64 + lane] : z4;

    float sim[RPW];
    float psum = 0.0f, pcnt = 0.0f;
    #pragma unroll
    for (int i = 0; i < RPW; ++i) {
        float dot = x0[i].x * v0.x + x0[i].y * v0.y + x0[i].z * v0.z + x0[i].w * v0.w
                  + x1[i].x * v1.x + x1[i].y * v1.y + x1[i].z * v1.z + x1[i].w * v1.w
                  + x2[i].x * v2.x + x2[i].y * v2.y + x2[i].z * v2.z + x2[i].w * v2.w;
        #pragma unroll
        for (int o = 16; o > 0; o >>= 1) dot += __shfl_xor_sync(0xffffffffu, dot, o);
        sim[i] = bfac[i] * dot;
        if (lane == 0) {
            out_sim[base + i] = sim[i];
            if (cls[i]) { psum += sim[i]; pcnt += 1.0f; }
        }
    }
    if (lane == 0) { s_ms[warp] = psum; s_mc[warp] = pcnt; }
    __syncthreads();
    if (tid == 0) {
        float bs = 0.0f, bc = 0.0f;
        #pragma unroll
        for (int w = 0; w < 16; ++w) { bs += s_ms[w]; bc += s_mc[w]; }
        g_msum_p[blockIdx.x] = bs;
        g_mcnt_p[blockIdx.x] = bc;
    }

    gridbar(2);

    if (warp == 0) {
        float bs = 0.0f, bc = 0.0f;
        #pragma unroll
        for (int j = 0; j < FBLK / 32; ++j) {
            bs += *(volatile float*)&g_msum_p[lane + 32 * j];
            bc += *(volatile float*)&g_mcnt_p[lane + 32 * j];
        }
        #pragma unroll
        for (int o = 16; o > 0; o >>= 1) {
            bs += __shfl_xor_sync(0xffffffffu, bs, o);
            bc += __shfl_xor_sync(0xffffffffu, bc, o);
        }
        if (lane == 0) s_mean = bs / fmaxf(bc, 1.0f);
    }
    __syncthreads();
    float mean = s_mean;
    if (lane == 0) {
        #pragma unroll
        for (int i = 0; i < RPW; ++i)
            out_clean[base + i] = ((sim[i] > mean) && cls[i]) ? 1.0f : 0.0f;
    }
}

// ---------------- launch ----------------
extern "C" void kernel_launch(void* const* d_in, const int* in_sizes, int n_in,
                              void* d_out, int out_size) {
    const float* feat  = (const float*)d_in[0];
    const float* label = (const float*)d_in[1];
    const int*   clab  = (const int*)d_in[2];
    float* out = (float*)d_out;
    float* out_cm    = out;
    float* out_sim   = out + (size_t)SS * DD;
    float* out_clean = out + (size_t)SS * DD + SS;

    k_counts<<<KK, 1024>>>(label, clab);
    k_gather<<<GBLK, 512>>>(feat, out_cm);
    k_fused<<<FBLK, FTPB>>>(out_cm, out_sim, out_clean);
}